// round 6
// baseline (speedup 1.0000x reference)
#include <cuda_runtime.h>
#include <cuda_fp16.h>
#include <math.h>

#define N0 8192
#define N1 4096
#define N2 8192
// W0: [N0, N1] row-major, W1: [N1, N2] row-major

// Persistent state (device globals — allocation-free scratch)
__device__ float g_x1[N1];
__device__ float g_x2[N2];
__device__ float g_e1[N1];
__device__ float g_g1[N1];
__device__ float g_g2[N2];
__device__ int   g_ctr;
// fp16 weight copies (written once in step 1, read in steps 2..9 + final)
__device__ __half g_W0h[(size_t)N0 * N1];   // 64 MB
__device__ __half g_W1h[(size_t)N1 * N2];   // 64 MB

__device__ __forceinline__ float dot4(float4 a, float4 b) {
    return a.x * b.x + a.y * b.y + a.z * b.z + a.w * b.w;
}
// dot of 8 halfs (uint4) with 8 floats, fp32 accumulate
__device__ __forceinline__ float dot8(uint4 w, const float* x) {
    const __half2* h = (const __half2*)&w;
    float s = 0.f;
#pragma unroll
    for (int j = 0; j < 4; j++) {
        float2 v = __half22float2(h[j]);
        s += v.x * x[2 * j] + v.y * x[2 * j + 1];
    }
    return s;
}
// a[0..8) += e * w
__device__ __forceinline__ void axpy8(uint4 w, float e, float* a) {
    const __half2* h = (const __half2*)&w;
#pragma unroll
    for (int j = 0; j < 4; j++) {
        float2 v = __half22float2(h[j]);
        a[2 * j]     += e * v.x;
        a[2 * j + 1] += e * v.y;
    }
}
__device__ __forceinline__ uint2 f4_to_h4(float4 v) {
    __half2 a = __floats2half2_rn(v.x, v.y);
    __half2 b = __floats2half2_rn(v.z, v.w);
    uint2 u;
    u.x = *(unsigned*)&a;
    u.y = *(unsigned*)&b;
    return u;
}

// ---------------------------------------------------------------------------
__global__ void k_init(float* __restrict__ out) {
    int i = blockIdx.x * blockDim.x + threadIdx.x;
    if (i < N1) { g_x1[i] = 0.f; g_g1[i] = 0.f; g_e1[i] = 0.f; }
    if (i < N2) { g_x2[i] = 0.f; g_g2[i] = 0.f; }
    if (i == 0) { out[0] = 0.f; g_ctr = 0; }
}

// ---------------------------------------------------------------------------
// Fused state update by the LAST block (threadfence-reduction pattern).
// ---------------------------------------------------------------------------
__device__ __forceinline__ void step_epilogue(int nblocks) {
    __shared__ int is_last;
    __threadfence();
    if (threadIdx.x == 0) {
        int v = atomicAdd(&g_ctr, 1);
        is_last = (v == nblocks - 1);
    }
    __syncthreads();
    if (!is_last) return;
    __threadfence();
    const int tid = threadIdx.x;
    const int nt  = blockDim.x;
    for (int i = tid; i < N1; i += nt) {
        float gr = fminf(fmaxf(-g_e1[i] + g_g1[i], -1.f), 1.f);
        g_x1[i] = tanhf(g_x1[i] + 0.01f * gr);
        g_g1[i] = 0.f;
    }
    for (int i = tid; i < N2; i += nt) {
        float x2 = g_x2[i];
        float gr = fminf(fmaxf(-x2 + g_g2[i], -1.f), 1.f);
        g_x2[i] = tanhf(x2 + 0.01f * gr);
        g_g2[i] = 0.f;
    }
    if (tid == 0) g_ctr = 0;
}

// ---------------------------------------------------------------------------
// Step 1: fp32 fused step (W read once) + write fp16 copies + fused update.
// Blocks [0,128): W0 (64 rows). Blocks [128,256): W1 (32 rows). 512 threads.
// (Round-3 geometry — proven 62% DRAM, no spill.)
// ---------------------------------------------------------------------------
__global__ void __launch_bounds__(512) k_step1(const float* __restrict__ x0,
                                               const float* __restrict__ W0,
                                               const float* __restrict__ W1) {
    __shared__ float sp[8][16];
    __shared__ float se[8];
    const int tid  = threadIdx.x;
    const int warp = tid >> 5;
    const int lane = tid & 31;

    if (blockIdx.x < 128) {
        const int rowBase = blockIdx.x * 64;
        const float4* xv = (const float4*)g_x1;
        const float4 xA = xv[tid];
        const float4 xB = xv[tid + 512];
        float4 accA = make_float4(0, 0, 0, 0);
        float4 accB = make_float4(0, 0, 0, 0);

        #pragma unroll 1
        for (int t = 0; t < 8; t++) {
            const int rb = rowBase + t * 8;
            const float4* base = (const float4*)W0 + (size_t)rb * 1024 + tid;
            float4 wA[8], wB[8];
            #pragma unroll
            for (int r = 0; r < 8; r++) {
                wA[r] = base[(size_t)r * 1024];
                wB[r] = base[(size_t)r * 1024 + 512];
            }
            #pragma unroll
            for (int r = 0; r < 8; r++) {
                uint2* dst = (uint2*)g_W0h + (size_t)(rb + r) * 1024;
                dst[tid]       = f4_to_h4(wA[r]);
                dst[tid + 512] = f4_to_h4(wB[r]);
            }
            #pragma unroll
            for (int r = 0; r < 8; r++) {
                float p = dot4(wA[r], xA) + dot4(wB[r], xB);
                #pragma unroll
                for (int o = 16; o; o >>= 1) p += __shfl_xor_sync(0xFFFFFFFFu, p, o);
                if (lane == 0) sp[r][warp] = p;
            }
            __syncthreads();
            if (tid < 8) {
                float s = 0.f;
                #pragma unroll
                for (int w = 0; w < 16; w++) s += sp[tid][w];
                se[tid] = x0[rb + tid] - tanhf(s);
            }
            __syncthreads();
            #pragma unroll
            for (int r = 0; r < 8; r++) {
                const float e = se[r];
                accA.x += e * wA[r].x;  accA.y += e * wA[r].y;
                accA.z += e * wA[r].z;  accA.w += e * wA[r].w;
                accB.x += e * wB[r].x;  accB.y += e * wB[r].y;
                accB.z += e * wB[r].z;  accB.w += e * wB[r].w;
            }
        }
        const int cA = 4 * tid;
        const int cB = 4 * (tid + 512);
        atomicAdd(&g_g1[cA + 0], accA.x);
        atomicAdd(&g_g1[cA + 1], accA.y);
        atomicAdd(&g_g1[cA + 2], accA.z);
        atomicAdd(&g_g1[cA + 3], accA.w);
        atomicAdd(&g_g1[cB + 0], accB.x);
        atomicAdd(&g_g1[cB + 1], accB.y);
        atomicAdd(&g_g1[cB + 2], accB.z);
        atomicAdd(&g_g1[cB + 3], accB.w);
    } else {
        const int rowBase = (blockIdx.x - 128) * 32;
        const float4* xv = (const float4*)g_x2;
        float4 xC[4];
        #pragma unroll
        for (int k = 0; k < 4; k++) xC[k] = xv[tid + k * 512];
        float4 acc[4] = {make_float4(0,0,0,0), make_float4(0,0,0,0),
                         make_float4(0,0,0,0), make_float4(0,0,0,0)};

        #pragma unroll 1
        for (int t = 0; t < 8; t++) {
            const int rb = rowBase + t * 4;
            const float4* base = (const float4*)W1 + (size_t)rb * 2048 + tid;
            float4 w[4][4];
            #pragma unroll
            for (int r = 0; r < 4; r++)
                #pragma unroll
                for (int k = 0; k < 4; k++)
                    w[r][k] = base[(size_t)r * 2048 + k * 512];
            #pragma unroll
            for (int r = 0; r < 4; r++) {
                uint2* dst = (uint2*)g_W1h + (size_t)(rb + r) * 2048;
                #pragma unroll
                for (int k = 0; k < 4; k++)
                    dst[tid + k * 512] = f4_to_h4(w[r][k]);
            }
            #pragma unroll
            for (int r = 0; r < 4; r++) {
                float p = dot4(w[r][0], xC[0]) + dot4(w[r][1], xC[1])
                        + dot4(w[r][2], xC[2]) + dot4(w[r][3], xC[3]);
                #pragma unroll
                for (int o = 16; o; o >>= 1) p += __shfl_xor_sync(0xFFFFFFFFu, p, o);
                if (lane == 0) sp[r][warp] = p;
            }
            __syncthreads();
            if (tid < 4) {
                float s = 0.f;
                #pragma unroll
                for (int wi = 0; wi < 16; wi++) s += sp[tid][wi];
                float e = g_x1[rb + tid] - tanhf(s);
                se[tid] = e;
                g_e1[rb + tid] = e;
            }
            __syncthreads();
            #pragma unroll
            for (int r = 0; r < 4; r++) {
                const float e = se[r];
                #pragma unroll
                for (int k = 0; k < 4; k++) {
                    acc[k].x += e * w[r][k].x;  acc[k].y += e * w[r][k].y;
                    acc[k].z += e * w[r][k].z;  acc[k].w += e * w[r][k].w;
                }
            }
        }
        #pragma unroll
        for (int k = 0; k < 4; k++) {
            const int c = 4 * (tid + k * 512);
            atomicAdd(&g_g2[c + 0], acc[k].x);
            atomicAdd(&g_g2[c + 1], acc[k].y);
            atomicAdd(&g_g2[c + 2], acc[k].z);
            atomicAdd(&g_g2[c + 3], acc[k].w);
        }
    }
    step_epilogue(256);
}

// ---------------------------------------------------------------------------
// Steps 2..9: fp16 fused step, 512 threads, SMALL tiles (spill-proof):
//   Blocks [0,256):   W0h, 32 rows each; tile = 8 rows, 1 uint4/row/thread
//                     (w: 32 regs, xf: 8, acc: 8)
//   Blocks [256,512): W1h, 16 rows each; tile = 4 rows, 2 uint4/row/thread
//                     (w: 32 regs, xf: 16, acc: 16)
// Uniform 256 KB per block.
// ---------------------------------------------------------------------------
__global__ void __launch_bounds__(512) k_step_h(const float* __restrict__ x0) {
    __shared__ float sp[8][16];
    __shared__ float se[8];
    const int tid  = threadIdx.x;
    const int warp = tid >> 5;
    const int lane = tid & 31;

    if (blockIdx.x < 256) {
        // ------------- W0h: [8192 x 4096] halfs, row = 512 uint4 -----------
        const int rowBase = blockIdx.x * 32;
        const uint4* W = (const uint4*)g_W0h;
        float xf[8];
        {
            const float4* xv = (const float4*)g_x1;
            float4 a = xv[2 * tid], b = xv[2 * tid + 1];
            xf[0]=a.x; xf[1]=a.y; xf[2]=a.z; xf[3]=a.w;
            xf[4]=b.x; xf[5]=b.y; xf[6]=b.z; xf[7]=b.w;
        }
        float acc[8];
        #pragma unroll
        for (int j = 0; j < 8; j++) acc[j] = 0.f;

        #pragma unroll 1
        for (int t = 0; t < 4; t++) {
            const int rb = rowBase + t * 8;
            const uint4* base = W + (size_t)rb * 512 + tid;
            uint4 w[8];
            #pragma unroll
            for (int r = 0; r < 8; r++) w[r] = base[(size_t)r * 512];

            #pragma unroll
            for (int r = 0; r < 8; r++) {
                float p = dot8(w[r], xf);
                #pragma unroll
                for (int o = 16; o; o >>= 1) p += __shfl_xor_sync(0xFFFFFFFFu, p, o);
                if (lane == 0) sp[r][warp] = p;
            }
            __syncthreads();
            if (tid < 128) {
                const int r = tid >> 4, wi = tid & 15;
                float v = sp[r][wi];
                v += __shfl_xor_sync(0xFFFFFFFFu, v, 8);
                v += __shfl_xor_sync(0xFFFFFFFFu, v, 4);
                v += __shfl_xor_sync(0xFFFFFFFFu, v, 2);
                v += __shfl_xor_sync(0xFFFFFFFFu, v, 1);
                if (wi == 0) se[r] = x0[rb + r] - tanhf(v);
            }
            __syncthreads();
            #pragma unroll
            for (int r = 0; r < 8; r++) axpy8(w[r], se[r], acc);
        }
        #pragma unroll
        for (int j = 0; j < 8; j++) atomicAdd(&g_g1[8 * tid + j], acc[j]);
    } else {
        // ------------- W1h: [4096 x 8192] halfs, row = 1024 uint4 ----------
        const int rowBase = (blockIdx.x - 256) * 16;
        const uint4* W = (const uint4*)g_W1h;
        float xfA[8], xfB[8];
        {
            const float4* xv = (const float4*)g_x2;
            float4 a = xv[2 * tid],         b = xv[2 * tid + 1];
            float4 c = xv[2 * (tid + 512)], d = xv[2 * (tid + 512) + 1];
            xfA[0]=a.x; xfA[1]=a.y; xfA[2]=a.z; xfA[3]=a.w;
            xfA[4]=b.x; xfA[5]=b.y; xfA[6]=b.z; xfA[7]=b.w;
            xfB[0]=c.x; xfB[1]=c.y; xfB[2]=c.z; xfB[3]=c.w;
            xfB[4]=d.x; xfB[5]=d.y; xfB[6]=d.z; xfB[7]=d.w;
        }
        float accA[8], accB[8];
        #pragma unroll
        for (int j = 0; j < 8; j++) { accA[j] = 0.f; accB[j] = 0.f; }

        #pragma unroll 1
        for (int t = 0; t < 4; t++) {
            const int rb = rowBase + t * 4;
            const uint4* base = W + (size_t)rb * 1024 + tid;
            uint4 wA[4], wB[4];
            #pragma unroll
            for (int r = 0; r < 4; r++) {
                wA[r] = base[(size_t)r * 1024];
                wB[r] = base[(size_t)r * 1024 + 512];
            }
            #pragma unroll
            for (int r = 0; r < 4; r++) {
                float p = dot8(wA[r], xfA) + dot8(wB[r], xfB);
                #pragma unroll
                for (int o = 16; o; o >>= 1) p += __shfl_xor_sync(0xFFFFFFFFu, p, o);
                if (lane == 0) sp[r][warp] = p;
            }
            __syncthreads();
            if (tid < 64) {
                const int r = tid >> 4, wi = tid & 15;
                float v = sp[r][wi];
                v += __shfl_xor_sync(0xFFFFFFFFu, v, 8);
                v += __shfl_xor_sync(0xFFFFFFFFu, v, 4);
                v += __shfl_xor_sync(0xFFFFFFFFu, v, 2);
                v += __shfl_xor_sync(0xFFFFFFFFu, v, 1);
                if (wi == 0) {
                    float e = g_x1[rb + r] - tanhf(v);
                    se[r] = e;
                    g_e1[rb + r] = e;
                }
            }
            __syncthreads();
            #pragma unroll
            for (int r = 0; r < 4; r++) {
                const float e = se[r];
                axpy8(wA[r], e, accA);
                axpy8(wB[r], e, accB);
            }
        }
        #pragma unroll
        for (int j = 0; j < 8; j++) atomicAdd(&g_g2[8 * tid + j], accA[j]);
        #pragma unroll
        for (int j = 0; j < 8; j++) atomicAdd(&g_g2[8 * (tid + 512) + j], accB[j]);
    }
    step_epilogue(512);
}

// ---------------------------------------------------------------------------
// Final: err = ||x0 - tanh(W0@x1)||^2 + ||x1 - tanh(W1@x2)||^2 + ||x2||^2
// fp16 weights, warp-per-row.
// ---------------------------------------------------------------------------
__global__ void __launch_bounds__(256) k_final_h(const float* __restrict__ x0,
                                                 float* __restrict__ out) {
    __shared__ float s_part[8];
    const int warpInBlock = threadIdx.x >> 5;
    const int warp = (blockIdx.x * blockDim.x + threadIdx.x) >> 5;
    const int lane = threadIdx.x & 31;

    float local = 0.f;
    if (warp < N0) {
        const uint4* row = (const uint4*)g_W0h + (size_t)warp * 512;
        const float4* xv = (const float4*)g_x1;
        float acc = 0.f;
        #pragma unroll 4
        for (int i = lane; i < 512; i += 32) {
            uint4 w = row[i];
            float4 a = xv[2 * i], b = xv[2 * i + 1];
            float xf[8] = {a.x, a.y, a.z, a.w, b.x, b.y, b.z, b.w};
            acc += dot8(w, xf);
        }
        #pragma unroll
        for (int o = 16; o; o >>= 1) acc += __shfl_xor_sync(0xFFFFFFFFu, acc, o);
        if (lane == 0) {
            float e = x0[warp] - tanhf(acc);
            float x2v = g_x2[warp];
            local = e * e + x2v * x2v;
        }
    } else {
        const int r = warp - N0;
        const uint4* row = (const uint4*)g_W1h + (size_t)r * 1024;
        const float4* xv = (const float4*)g_x2;
        float acc = 0.f;
        #pragma unroll 4
        for (int i = lane; i < 1024; i += 32) {
            uint4 w = row[i];
            float4 a = xv[2 * i], b = xv[2 * i + 1];
            float xf[8] = {a.x, a.y, a.z, a.w, b.x, b.y, b.z, b.w};
            acc += dot8(w, xf);
        }
        #pragma unroll
        for (int o = 16; o; o >>= 1) acc += __shfl_xor_sync(0xFFFFFFFFu, acc, o);
        if (lane == 0) {
            float e = g_x1[r] - tanhf(acc);
            local = e * e;
        }
    }

    if (lane == 0) s_part[warpInBlock] = local;
    __syncthreads();
    if (threadIdx.x == 0) {
        float s = 0.f;
        #pragma unroll
        for (int w = 0; w < 8; w++) s += s_part[w];
        atomicAdd(out, s);
    }
}

// ---------------------------------------------------------------------------
extern "C" void kernel_launch(void* const* d_in, const int* in_sizes, int n_in,
                              void* d_out, int out_size) {
    const float* x0 = (const float*)d_in[0];
    const float* W0 = (const float*)d_in[1];
    const float* W1 = (const float*)d_in[2];
    float* out = (float*)d_out;

    k_init<<<32, 256>>>(out);
    k_step1<<<256, 512>>>(x0, W0, W1);          // fp32 step + fp16 conversion
    for (int s = 0; s < 8; s++)
        k_step_h<<<512, 512>>>(x0);             // fp16 steps 2..9
    k_final_h<<<(N0 + N1) / 8, 256>>>(x0, out); // fp16 final error
}

// round 7
// speedup vs baseline: 1.0699x; 1.0699x over previous
#include <cuda_runtime.h>
#include <cuda_fp16.h>
#include <math.h>

#define N0 8192
#define N1 4096
#define N2 8192
// W0: [N0, N1] row-major, W1: [N1, N2] row-major

// Persistent state (device globals — allocation-free scratch)
__device__ float g_x1[N1];
__device__ float g_x2[N2];
__device__ float g_e1[N1];
__device__ float g_g1[N1];
__device__ float g_g2[N2];
__device__ int   g_ctr;
// fp16 weight copies (written once in step 1, read in steps 2..9 + final)
__device__ __half g_W0h[(size_t)N0 * N1];   // 64 MB
__device__ __half g_W1h[(size_t)N1 * N2];   // 64 MB

__device__ __forceinline__ float dot4(float4 a, float4 b) {
    return a.x * b.x + a.y * b.y + a.z * b.z + a.w * b.w;
}
// dot of 8 halfs (uint4) with 8 floats, fp32 accumulate
__device__ __forceinline__ float dot8(uint4 w, const float* x) {
    const __half2* h = (const __half2*)&w;
    float s = 0.f;
#pragma unroll
    for (int j = 0; j < 4; j++) {
        float2 v = __half22float2(h[j]);
        s += v.x * x[2 * j] + v.y * x[2 * j + 1];
    }
    return s;
}
// a[0..8) += e * w
__device__ __forceinline__ void axpy8(uint4 w, float e, float* a) {
    const __half2* h = (const __half2*)&w;
#pragma unroll
    for (int j = 0; j < 4; j++) {
        float2 v = __half22float2(h[j]);
        a[2 * j]     += e * v.x;
        a[2 * j + 1] += e * v.y;
    }
}
__device__ __forceinline__ uint2 f4_to_h4(float4 v) {
    __half2 a = __floats2half2_rn(v.x, v.y);
    __half2 b = __floats2half2_rn(v.z, v.w);
    uint2 u;
    u.x = *(unsigned*)&a;
    u.y = *(unsigned*)&b;
    return u;
}

// ---------------------------------------------------------------------------
__global__ void k_init(float* __restrict__ out) {
    int i = blockIdx.x * blockDim.x + threadIdx.x;
    if (i < N1) { g_x1[i] = 0.f; g_g1[i] = 0.f; g_e1[i] = 0.f; }
    if (i < N2) { g_x2[i] = 0.f; g_g2[i] = 0.f; }
    if (i == 0) { out[0] = 0.f; g_ctr = 0; }
}

// ---------------------------------------------------------------------------
// Fused state update by the LAST block (threadfence-reduction pattern).
// ---------------------------------------------------------------------------
__device__ __forceinline__ void step_epilogue(int nblocks) {
    __shared__ int is_last;
    __threadfence();
    if (threadIdx.x == 0) {
        int v = atomicAdd(&g_ctr, 1);
        is_last = (v == nblocks - 1);
    }
    __syncthreads();
    if (!is_last) return;
    __threadfence();
    const int tid = threadIdx.x;
    const int nt  = blockDim.x;
    for (int i = tid; i < N1; i += nt) {
        float gr = fminf(fmaxf(-g_e1[i] + g_g1[i], -1.f), 1.f);
        g_x1[i] = tanhf(g_x1[i] + 0.01f * gr);
        g_g1[i] = 0.f;
    }
    for (int i = tid; i < N2; i += nt) {
        float x2 = g_x2[i];
        float gr = fminf(fmaxf(-x2 + g_g2[i], -1.f), 1.f);
        g_x2[i] = tanhf(x2 + 0.01f * gr);
        g_g2[i] = 0.f;
    }
    if (tid == 0) g_ctr = 0;
}

// ---------------------------------------------------------------------------
// Step 1: fp32 fused step (W read once) + write fp16 copies + fused update.
// Blocks [0,128): W0 (64 rows). Blocks [128,256): W1 (32 rows). 512 threads.
// (Round-3 geometry — proven, no spill.)
// ---------------------------------------------------------------------------
__global__ void __launch_bounds__(512) k_step1(const float* __restrict__ x0,
                                               const float* __restrict__ W0,
                                               const float* __restrict__ W1) {
    __shared__ float sp[8][16];
    __shared__ float se[8];
    const int tid  = threadIdx.x;
    const int warp = tid >> 5;
    const int lane = tid & 31;

    if (blockIdx.x < 128) {
        const int rowBase = blockIdx.x * 64;
        const float4* xv = (const float4*)g_x1;
        const float4 xA = xv[tid];
        const float4 xB = xv[tid + 512];
        float4 accA = make_float4(0, 0, 0, 0);
        float4 accB = make_float4(0, 0, 0, 0);

        #pragma unroll 1
        for (int t = 0; t < 8; t++) {
            const int rb = rowBase + t * 8;
            const float4* base = (const float4*)W0 + (size_t)rb * 1024 + tid;
            float4 wA[8], wB[8];
            #pragma unroll
            for (int r = 0; r < 8; r++) {
                wA[r] = base[(size_t)r * 1024];
                wB[r] = base[(size_t)r * 1024 + 512];
            }
            #pragma unroll
            for (int r = 0; r < 8; r++) {
                uint2* dst = (uint2*)g_W0h + (size_t)(rb + r) * 1024;
                dst[tid]       = f4_to_h4(wA[r]);
                dst[tid + 512] = f4_to_h4(wB[r]);
            }
            #pragma unroll
            for (int r = 0; r < 8; r++) {
                float p = dot4(wA[r], xA) + dot4(wB[r], xB);
                #pragma unroll
                for (int o = 16; o; o >>= 1) p += __shfl_xor_sync(0xFFFFFFFFu, p, o);
                if (lane == 0) sp[r][warp] = p;
            }
            __syncthreads();
            if (tid < 8) {
                float s = 0.f;
                #pragma unroll
                for (int w = 0; w < 16; w++) s += sp[tid][w];
                se[tid] = x0[rb + tid] - tanhf(s);
            }
            __syncthreads();
            #pragma unroll
            for (int r = 0; r < 8; r++) {
                const float e = se[r];
                accA.x += e * wA[r].x;  accA.y += e * wA[r].y;
                accA.z += e * wA[r].z;  accA.w += e * wA[r].w;
                accB.x += e * wB[r].x;  accB.y += e * wB[r].y;
                accB.z += e * wB[r].z;  accB.w += e * wB[r].w;
            }
        }
        const int cA = 4 * tid;
        const int cB = 4 * (tid + 512);
        atomicAdd(&g_g1[cA + 0], accA.x);
        atomicAdd(&g_g1[cA + 1], accA.y);
        atomicAdd(&g_g1[cA + 2], accA.z);
        atomicAdd(&g_g1[cA + 3], accA.w);
        atomicAdd(&g_g1[cB + 0], accB.x);
        atomicAdd(&g_g1[cB + 1], accB.y);
        atomicAdd(&g_g1[cB + 2], accB.z);
        atomicAdd(&g_g1[cB + 3], accB.w);
    } else {
        const int rowBase = (blockIdx.x - 128) * 32;
        const float4* xv = (const float4*)g_x2;
        float4 xC[4];
        #pragma unroll
        for (int k = 0; k < 4; k++) xC[k] = xv[tid + k * 512];
        float4 acc[4] = {make_float4(0,0,0,0), make_float4(0,0,0,0),
                         make_float4(0,0,0,0), make_float4(0,0,0,0)};

        #pragma unroll 1
        for (int t = 0; t < 8; t++) {
            const int rb = rowBase + t * 4;
            const float4* base = (const float4*)W1 + (size_t)rb * 2048 + tid;
            float4 w[4][4];
            #pragma unroll
            for (int r = 0; r < 4; r++)
                #pragma unroll
                for (int k = 0; k < 4; k++)
                    w[r][k] = base[(size_t)r * 2048 + k * 512];
            #pragma unroll
            for (int r = 0; r < 4; r++) {
                uint2* dst = (uint2*)g_W1h + (size_t)(rb + r) * 2048;
                #pragma unroll
                for (int k = 0; k < 4; k++)
                    dst[tid + k * 512] = f4_to_h4(w[r][k]);
            }
            #pragma unroll
            for (int r = 0; r < 4; r++) {
                float p = dot4(w[r][0], xC[0]) + dot4(w[r][1], xC[1])
                        + dot4(w[r][2], xC[2]) + dot4(w[r][3], xC[3]);
                #pragma unroll
                for (int o = 16; o; o >>= 1) p += __shfl_xor_sync(0xFFFFFFFFu, p, o);
                if (lane == 0) sp[r][warp] = p;
            }
            __syncthreads();
            if (tid < 4) {
                float s = 0.f;
                #pragma unroll
                for (int wi = 0; wi < 16; wi++) s += sp[tid][wi];
                float e = g_x1[rb + tid] - tanhf(s);
                se[tid] = e;
                g_e1[rb + tid] = e;
            }
            __syncthreads();
            #pragma unroll
            for (int r = 0; r < 4; r++) {
                const float e = se[r];
                #pragma unroll
                for (int k = 0; k < 4; k++) {
                    acc[k].x += e * w[r][k].x;  acc[k].y += e * w[r][k].y;
                    acc[k].z += e * w[r][k].z;  acc[k].w += e * w[r][k].w;
                }
            }
        }
        #pragma unroll
        for (int k = 0; k < 4; k++) {
            const int c = 4 * (tid + k * 512);
            atomicAdd(&g_g2[c + 0], acc[k].x);
            atomicAdd(&g_g2[c + 1], acc[k].y);
            atomicAdd(&g_g2[c + 2], acc[k].z);
            atomicAdd(&g_g2[c + 3], acc[k].w);
        }
    }
    step_epilogue(256);
}

// ---------------------------------------------------------------------------
// fp16 W0 kernel (steps 2..9 first half): e0 + g1 = W0h^T e0.
// grid 128 x 512 thr. Block = 64 rows = 4 tiles x 16 rows.
// Thread owns 1 uint4 (8 cols) per row: 16 LDG.128 per tile (round-3 depth).
// Live set: w[16]=64 regs, xf 8, acc 8 -> ~100 regs, no spill.
// ---------------------------------------------------------------------------
__global__ void __launch_bounds__(512) k_w0(const float* __restrict__ x0) {
    __shared__ float sp[16][16];
    __shared__ float se[16];
    const int tid  = threadIdx.x;
    const int warp = tid >> 5;
    const int lane = tid & 31;

    const int rowBase = blockIdx.x * 64;
    const uint4* W = (const uint4*)g_W0h;
    float xf[8];
    {
        const float4* xv = (const float4*)g_x1;
        float4 a = xv[2 * tid], b = xv[2 * tid + 1];
        xf[0]=a.x; xf[1]=a.y; xf[2]=a.z; xf[3]=a.w;
        xf[4]=b.x; xf[5]=b.y; xf[6]=b.z; xf[7]=b.w;
    }
    float acc[8];
    #pragma unroll
    for (int j = 0; j < 8; j++) acc[j] = 0.f;

    #pragma unroll 1
    for (int t = 0; t < 4; t++) {
        const int rb = rowBase + t * 16;
        const uint4* base = W + (size_t)rb * 512 + tid;
        uint4 w[16];
        #pragma unroll
        for (int r = 0; r < 16; r++) w[r] = base[(size_t)r * 512];

        #pragma unroll
        for (int r = 0; r < 16; r++) {
            float p = dot8(w[r], xf);
            #pragma unroll
            for (int o = 16; o; o >>= 1) p += __shfl_xor_sync(0xFFFFFFFFu, p, o);
            if (lane == 0) sp[r][warp] = p;
        }
        __syncthreads();
        if (tid < 256) {
            const int r = tid >> 4, wi = tid & 15;
            float v = sp[r][wi];
            v += __shfl_xor_sync(0xFFFFFFFFu, v, 8);
            v += __shfl_xor_sync(0xFFFFFFFFu, v, 4);
            v += __shfl_xor_sync(0xFFFFFFFFu, v, 2);
            v += __shfl_xor_sync(0xFFFFFFFFu, v, 1);
            if (wi == 0) se[r] = x0[rb + r] - tanhf(v);
        }
        __syncthreads();
        #pragma unroll
        for (int r = 0; r < 16; r++) axpy8(w[r], se[r], acc);
    }
    #pragma unroll
    for (int j = 0; j < 8; j++) atomicAdd(&g_g1[8 * tid + j], acc[j]);
}

// ---------------------------------------------------------------------------
// fp16 W1 kernel (steps 2..9 second half): e1 + g2 = W1h^T e1, then the
// fused state update in the last block. Runs after k_w0 (stream order
// guarantees g1 is complete).
// grid 128 x 512 thr. Block = 32 rows = 4 tiles x 8 rows.
// Thread owns 2 uint4 per row: 16 LDG.128 per tile.
// Live set: w 64 regs, xf 16, acc 16 -> ~110 regs, no spill.
// ---------------------------------------------------------------------------
__global__ void __launch_bounds__(512) k_w1() {
    __shared__ float sp[8][16];
    __shared__ float se[8];
    const int tid  = threadIdx.x;
    const int warp = tid >> 5;
    const int lane = tid & 31;

    const int rowBase = blockIdx.x * 32;
    const uint4* W = (const uint4*)g_W1h;
    float xfA[8], xfB[8];
    {
        const float4* xv = (const float4*)g_x2;
        float4 a = xv[2 * tid],         b = xv[2 * tid + 1];
        float4 c = xv[2 * (tid + 512)], d = xv[2 * (tid + 512) + 1];
        xfA[0]=a.x; xfA[1]=a.y; xfA[2]=a.z; xfA[3]=a.w;
        xfA[4]=b.x; xfA[5]=b.y; xfA[6]=b.z; xfA[7]=b.w;
        xfB[0]=c.x; xfB[1]=c.y; xfB[2]=c.z; xfB[3]=c.w;
        xfB[4]=d.x; xfB[5]=d.y; xfB[6]=d.z; xfB[7]=d.w;
    }
    float accA[8], accB[8];
    #pragma unroll
    for (int j = 0; j < 8; j++) { accA[j] = 0.f; accB[j] = 0.f; }

    #pragma unroll 1
    for (int t = 0; t < 4; t++) {
        const int rb = rowBase + t * 8;
        const uint4* base = W + (size_t)rb * 1024 + tid;
        uint4 wA[8], wB[8];
        #pragma unroll
        for (int r = 0; r < 8; r++) {
            wA[r] = base[(size_t)r * 1024];
            wB[r] = base[(size_t)r * 1024 + 512];
        }
        #pragma unroll
        for (int r = 0; r < 8; r++) {
            float p = dot8(wA[r], xfA) + dot8(wB[r], xfB);
            #pragma unroll
            for (int o = 16; o; o >>= 1) p += __shfl_xor_sync(0xFFFFFFFFu, p, o);
            if (lane == 0) sp[r][warp] = p;
        }
        __syncthreads();
        if (tid < 128) {
            const int r = tid >> 4, wi = tid & 15;
            float v = sp[r][wi];
            v += __shfl_xor_sync(0xFFFFFFFFu, v, 8);
            v += __shfl_xor_sync(0xFFFFFFFFu, v, 4);
            v += __shfl_xor_sync(0xFFFFFFFFu, v, 2);
            v += __shfl_xor_sync(0xFFFFFFFFu, v, 1);
            if (wi == 0) {
                float e = g_x1[rb + r] - tanhf(v);
                se[r] = e;
                g_e1[rb + r] = e;
            }
        }
        __syncthreads();
        #pragma unroll
        for (int r = 0; r < 8; r++) {
            const float e = se[r];
            axpy8(wA[r], e, accA);
            axpy8(wB[r], e, accB);
        }
    }
    #pragma unroll
    for (int j = 0; j < 8; j++) atomicAdd(&g_g2[8 * tid + j], accA[j]);
    #pragma unroll
    for (int j = 0; j < 8; j++) atomicAdd(&g_g2[8 * (tid + 512) + j], accB[j]);

    step_epilogue(128);
}

// ---------------------------------------------------------------------------
// Final: err = ||x0 - tanh(W0@x1)||^2 + ||x1 - tanh(W1@x2)||^2 + ||x2||^2
// fp16 weights, warp-per-row.
// ---------------------------------------------------------------------------
__global__ void __launch_bounds__(256) k_final_h(const float* __restrict__ x0,
                                                 float* __restrict__ out) {
    __shared__ float s_part[8];
    const int warpInBlock = threadIdx.x >> 5;
    const int warp = (blockIdx.x * blockDim.x + threadIdx.x) >> 5;
    const int lane = threadIdx.x & 31;

    float local = 0.f;
    if (warp < N0) {
        const uint4* row = (const uint4*)g_W0h + (size_t)warp * 512;
        const float4* xv = (const float4*)g_x1;
        float acc = 0.f;
        #pragma unroll 4
        for (int i = lane; i < 512; i += 32) {
            uint4 w = row[i];
            float4 a = xv[2 * i], b = xv[2 * i + 1];
            float xf[8] = {a.x, a.y, a.z, a.w, b.x, b.y, b.z, b.w};
            acc += dot8(w, xf);
        }
        #pragma unroll
        for (int o = 16; o; o >>= 1) acc += __shfl_xor_sync(0xFFFFFFFFu, acc, o);
        if (lane == 0) {
            float e = x0[warp] - tanhf(acc);
            float x2v = g_x2[warp];
            local = e * e + x2v * x2v;
        }
    } else {
        const int r = warp - N0;
        const uint4* row = (const uint4*)g_W1h + (size_t)r * 1024;
        const float4* xv = (const float4*)g_x2;
        float acc = 0.f;
        #pragma unroll 4
        for (int i = lane; i < 1024; i += 32) {
            uint4 w = row[i];
            float4 a = xv[2 * i], b = xv[2 * i + 1];
            float xf[8] = {a.x, a.y, a.z, a.w, b.x, b.y, b.z, b.w};
            acc += dot8(w, xf);
        }
        #pragma unroll
        for (int o = 16; o; o >>= 1) acc += __shfl_xor_sync(0xFFFFFFFFu, acc, o);
        if (lane == 0) {
            float e = g_x1[r] - tanhf(acc);
            local = e * e;
        }
    }

    if (lane == 0) s_part[warpInBlock] = local;
    __syncthreads();
    if (threadIdx.x == 0) {
        float s = 0.f;
        #pragma unroll
        for (int w = 0; w < 8; w++) s += s_part[w];
        atomicAdd(out, s);
    }
}

// ---------------------------------------------------------------------------
extern "C" void kernel_launch(void* const* d_in, const int* in_sizes, int n_in,
                              void* d_out, int out_size) {
    const float* x0 = (const float*)d_in[0];
    const float* W0 = (const float*)d_in[1];
    const float* W1 = (const float*)d_in[2];
    float* out = (float*)d_out;

    k_init<<<32, 256>>>(out);
    k_step1<<<256, 512>>>(x0, W0, W1);          // fp32 step + fp16 conversion
    for (int s = 0; s < 8; s++) {
        k_w0<<<128, 512>>>(x0);                 // e0 + g1 (fp16)
        k_w1<<<128, 512>>>();                   // e1 + g2 + fused update (fp16)
    }
    k_final_h<<<(N0 + N1) / 8, 256>>>(x0, out); // fp16 final error
}

// round 8
// speedup vs baseline: 1.2343x; 1.1536x over previous
#include <cuda_runtime.h>
#include <cuda_fp16.h>
#include <math.h>

#define N0 8192
#define N1 4096
#define N2 8192
// W0: [N0, N1] row-major, W1: [N1, N2] row-major

// Persistent state (device globals — allocation-free scratch)
__device__ float g_x1[N1];
__device__ float g_x2[N2];
__device__ float g_e1[N1];
__device__ float g_g1[N1];
__device__ float g_g2[N2];
__device__ int   g_ctr;
// fp16 weight copies (written once in step 1, read in steps 2..9 + final)
__device__ __half g_W0h[(size_t)N0 * N1];   // 64 MB
__device__ __half g_W1h[(size_t)N1 * N2];   // 64 MB

__device__ __forceinline__ float dot4(float4 a, float4 b) {
    return a.x * b.x + a.y * b.y + a.z * b.z + a.w * b.w;
}
// dot of 8 halfs (uint4) with 8 floats, fp32 accumulate
__device__ __forceinline__ float dot8(uint4 w, const float* x) {
    const __half2* h = (const __half2*)&w;
    float s = 0.f;
#pragma unroll
    for (int j = 0; j < 4; j++) {
        float2 v = __half22float2(h[j]);
        s += v.x * x[2 * j] + v.y * x[2 * j + 1];
    }
    return s;
}
// a[0..8) += e * w
__device__ __forceinline__ void axpy8(uint4 w, float e, float* a) {
    const __half2* h = (const __half2*)&w;
#pragma unroll
    for (int j = 0; j < 4; j++) {
        float2 v = __half22float2(h[j]);
        a[2 * j]     += e * v.x;
        a[2 * j + 1] += e * v.y;
    }
}
__device__ __forceinline__ uint2 f4_to_h4(float4 v) {
    __half2 a = __floats2half2_rn(v.x, v.y);
    __half2 b = __floats2half2_rn(v.z, v.w);
    uint2 u;
    u.x = *(unsigned*)&a;
    u.y = *(unsigned*)&b;
    return u;
}

// ---------------------------------------------------------------------------
__global__ void k_init(float* __restrict__ out) {
    int i = blockIdx.x * blockDim.x + threadIdx.x;
    if (i < N1) { g_x1[i] = 0.f; g_g1[i] = 0.f; g_e1[i] = 0.f; }
    if (i < N2) { g_x2[i] = 0.f; g_g2[i] = 0.f; }
    if (i == 0) { out[0] = 0.f; g_ctr = 0; }
}

// ---------------------------------------------------------------------------
// Fused state update by the LAST block (threadfence-reduction pattern).
// ---------------------------------------------------------------------------
__device__ __forceinline__ void step_epilogue(int nblocks) {
    __shared__ int is_last;
    __threadfence();
    if (threadIdx.x == 0) {
        int v = atomicAdd(&g_ctr, 1);
        is_last = (v == nblocks - 1);
    }
    __syncthreads();
    if (!is_last) return;
    __threadfence();
    const int tid = threadIdx.x;
    const int nt  = blockDim.x;
    for (int i = tid; i < N1; i += nt) {
        float gr = fminf(fmaxf(-g_e1[i] + g_g1[i], -1.f), 1.f);
        g_x1[i] = tanhf(g_x1[i] + 0.01f * gr);
        g_g1[i] = 0.f;
    }
    for (int i = tid; i < N2; i += nt) {
        float x2 = g_x2[i];
        float gr = fminf(fmaxf(-x2 + g_g2[i], -1.f), 1.f);
        g_x2[i] = tanhf(x2 + 0.01f * gr);
        g_g2[i] = 0.f;
    }
    if (tid == 0) g_ctr = 0;
}

// ---------------------------------------------------------------------------
// Step 1: fp32 fused step (W read once) + write fp16 copies + fused update.
// Blocks [0,128): W0 (64 rows). Blocks [128,256): W1 (32 rows). 512 threads.
// (Round-3 geometry — proven.)
// ---------------------------------------------------------------------------
__global__ void __launch_bounds__(512) k_step1(const float* __restrict__ x0,
                                               const float* __restrict__ W0,
                                               const float* __restrict__ W1) {
    __shared__ float sp[8][16];
    __shared__ float se[8];
    const int tid  = threadIdx.x;
    const int warp = tid >> 5;
    const int lane = tid & 31;

    if (blockIdx.x < 128) {
        const int rowBase = blockIdx.x * 64;
        const float4* xv = (const float4*)g_x1;
        const float4 xA = xv[tid];
        const float4 xB = xv[tid + 512];
        float4 accA = make_float4(0, 0, 0, 0);
        float4 accB = make_float4(0, 0, 0, 0);

        #pragma unroll 1
        for (int t = 0; t < 8; t++) {
            const int rb = rowBase + t * 8;
            const float4* base = (const float4*)W0 + (size_t)rb * 1024 + tid;
            float4 wA[8], wB[8];
            #pragma unroll
            for (int r = 0; r < 8; r++) {
                wA[r] = base[(size_t)r * 1024];
                wB[r] = base[(size_t)r * 1024 + 512];
            }
            #pragma unroll
            for (int r = 0; r < 8; r++) {
                uint2* dst = (uint2*)g_W0h + (size_t)(rb + r) * 1024;
                dst[tid]       = f4_to_h4(wA[r]);
                dst[tid + 512] = f4_to_h4(wB[r]);
            }
            #pragma unroll
            for (int r = 0; r < 8; r++) {
                float p = dot4(wA[r], xA) + dot4(wB[r], xB);
                #pragma unroll
                for (int o = 16; o; o >>= 1) p += __shfl_xor_sync(0xFFFFFFFFu, p, o);
                if (lane == 0) sp[r][warp] = p;
            }
            __syncthreads();
            if (tid < 8) {
                float s = 0.f;
                #pragma unroll
                for (int w = 0; w < 16; w++) s += sp[tid][w];
                se[tid] = x0[rb + tid] - tanhf(s);
            }
            __syncthreads();
            #pragma unroll
            for (int r = 0; r < 8; r++) {
                const float e = se[r];
                accA.x += e * wA[r].x;  accA.y += e * wA[r].y;
                accA.z += e * wA[r].z;  accA.w += e * wA[r].w;
                accB.x += e * wB[r].x;  accB.y += e * wB[r].y;
                accB.z += e * wB[r].z;  accB.w += e * wB[r].w;
            }
        }
        const int cA = 4 * tid;
        const int cB = 4 * (tid + 512);
        atomicAdd(&g_g1[cA + 0], accA.x);
        atomicAdd(&g_g1[cA + 1], accA.y);
        atomicAdd(&g_g1[cA + 2], accA.z);
        atomicAdd(&g_g1[cA + 3], accA.w);
        atomicAdd(&g_g1[cB + 0], accB.x);
        atomicAdd(&g_g1[cB + 1], accB.y);
        atomicAdd(&g_g1[cB + 2], accB.z);
        atomicAdd(&g_g1[cB + 3], accB.w);
    } else {
        const int rowBase = (blockIdx.x - 128) * 32;
        const float4* xv = (const float4*)g_x2;
        float4 xC[4];
        #pragma unroll
        for (int k = 0; k < 4; k++) xC[k] = xv[tid + k * 512];
        float4 acc[4] = {make_float4(0,0,0,0), make_float4(0,0,0,0),
                         make_float4(0,0,0,0), make_float4(0,0,0,0)};

        #pragma unroll 1
        for (int t = 0; t < 8; t++) {
            const int rb = rowBase + t * 4;
            const float4* base = (const float4*)W1 + (size_t)rb * 2048 + tid;
            float4 w[4][4];
            #pragma unroll
            for (int r = 0; r < 4; r++)
                #pragma unroll
                for (int k = 0; k < 4; k++)
                    w[r][k] = base[(size_t)r * 2048 + k * 512];
            #pragma unroll
            for (int r = 0; r < 4; r++) {
                uint2* dst = (uint2*)g_W1h + (size_t)(rb + r) * 2048;
                #pragma unroll
                for (int k = 0; k < 4; k++)
                    dst[tid + k * 512] = f4_to_h4(w[r][k]);
            }
            #pragma unroll
            for (int r = 0; r < 4; r++) {
                float p = dot4(w[r][0], xC[0]) + dot4(w[r][1], xC[1])
                        + dot4(w[r][2], xC[2]) + dot4(w[r][3], xC[3]);
                #pragma unroll
                for (int o = 16; o; o >>= 1) p += __shfl_xor_sync(0xFFFFFFFFu, p, o);
                if (lane == 0) sp[r][warp] = p;
            }
            __syncthreads();
            if (tid < 4) {
                float s = 0.f;
                #pragma unroll
                for (int wi = 0; wi < 16; wi++) s += sp[tid][wi];
                float e = g_x1[rb + tid] - tanhf(s);
                se[tid] = e;
                g_e1[rb + tid] = e;
            }
            __syncthreads();
            #pragma unroll
            for (int r = 0; r < 4; r++) {
                const float e = se[r];
                #pragma unroll
                for (int k = 0; k < 4; k++) {
                    acc[k].x += e * w[r][k].x;  acc[k].y += e * w[r][k].y;
                    acc[k].z += e * w[r][k].z;  acc[k].w += e * w[r][k].w;
                }
            }
        }
        #pragma unroll
        for (int k = 0; k < 4; k++) {
            const int c = 4 * (tid + k * 512);
            atomicAdd(&g_g2[c + 0], acc[k].x);
            atomicAdd(&g_g2[c + 1], acc[k].y);
            atomicAdd(&g_g2[c + 2], acc[k].z);
            atomicAdd(&g_g2[c + 3], acc[k].w);
        }
    }
    step_epilogue(256);
}

// ---------------------------------------------------------------------------
// Steps 2..9: fp16 fused step. 256 threads (reg cap 255 — no spill trap),
// register DOUBLE-BUFFERED: next tile's 8 LDG.128 are issued BEFORE the
// current tile's compute/barriers, keeping DRAM busy across the reduce.
// Blocks [0,128):   W0h, 64 rows = 16 tiles of 4 rows (2 uint4/row/thread).
// Blocks [128,256): W1h, 32 rows = 16 tiles of 2 rows (4 uint4/row/thread).
// ---------------------------------------------------------------------------
#define W0_TILE(CUR, NXT, RB, PREF, RBN)                                      \
  do {                                                                        \
    if (PREF) {                                                               \
      _Pragma("unroll")                                                       \
      for (int r = 0; r < 4; r++) {                                           \
        (NXT)[2*r]   = Wp[(size_t)((RBN) + r) * 512 + tid];                   \
        (NXT)[2*r+1] = Wp[(size_t)((RBN) + r) * 512 + tid + 256];             \
      }                                                                       \
    }                                                                         \
    _Pragma("unroll")                                                         \
    for (int r = 0; r < 4; r++) {                                             \
      float p = dot8((CUR)[2*r], xfA) + dot8((CUR)[2*r+1], xfB);              \
      _Pragma("unroll")                                                       \
      for (int o = 16; o; o >>= 1) p += __shfl_xor_sync(0xFFFFFFFFu, p, o);   \
      if (lane == 0) sp[r][warp] = p;                                         \
    }                                                                         \
    __syncthreads();                                                          \
    if (tid < 32) {                                                           \
      int r = tid >> 3, wi = tid & 7;                                         \
      float v = sp[r][wi];                                                    \
      v += __shfl_xor_sync(0xFFFFFFFFu, v, 4);                                \
      v += __shfl_xor_sync(0xFFFFFFFFu, v, 2);                                \
      v += __shfl_xor_sync(0xFFFFFFFFu, v, 1);                                \
      if (wi == 0) se[r] = x0[(RB) + r] - tanhf(v);                           \
    }                                                                         \
    __syncthreads();                                                          \
    _Pragma("unroll")                                                         \
    for (int r = 0; r < 4; r++) {                                             \
      axpy8((CUR)[2*r],   se[r], accA);                                       \
      axpy8((CUR)[2*r+1], se[r], accB);                                       \
    }                                                                         \
  } while (0)

#define W1_TILE(CUR, NXT, RB, PREF, RBN)                                      \
  do {                                                                        \
    if (PREF) {                                                               \
      _Pragma("unroll")                                                       \
      for (int r = 0; r < 2; r++)                                             \
        _Pragma("unroll")                                                     \
        for (int k = 0; k < 4; k++)                                           \
          (NXT)[4*r+k] = Wp[(size_t)((RBN) + r) * 1024 + tid + 256 * k];      \
    }                                                                         \
    _Pragma("unroll")                                                         \
    for (int r = 0; r < 2; r++) {                                             \
      float p = dot8((CUR)[4*r], xf) + dot8((CUR)[4*r+1], xf + 8)             \
              + dot8((CUR)[4*r+2], xf + 16) + dot8((CUR)[4*r+3], xf + 24);    \
      _Pragma("unroll")                                                       \
      for (int o = 16; o; o >>= 1) p += __shfl_xor_sync(0xFFFFFFFFu, p, o);   \
      if (lane == 0) sp[r][warp] = p;                                         \
    }                                                                         \
    __syncthreads();                                                          \
    if (tid < 16) {                                                           \
      int r = tid >> 3, wi = tid & 7;                                         \
      float v = sp[r][wi];                                                    \
      v += __shfl_xor_sync(0x0000FFFFu, v, 4);                                \
      v += __shfl_xor_sync(0x0000FFFFu, v, 2);                                \
      v += __shfl_xor_sync(0x0000FFFFu, v, 1);                                \
      if (wi == 0) {                                                          \
        float e = g_x1[(RB) + r] - tanhf(v);                                  \
        se[r] = e;                                                            \
        g_e1[(RB) + r] = e;                                                   \
      }                                                                       \
    }                                                                         \
    __syncthreads();                                                          \
    _Pragma("unroll")                                                         \
    for (int r = 0; r < 2; r++) {                                             \
      _Pragma("unroll")                                                       \
      for (int k = 0; k < 4; k++)                                             \
        axpy8((CUR)[4*r+k], se[r], acc + 8 * k);                              \
    }                                                                         \
  } while (0)

__global__ void __launch_bounds__(256) k_step_h(const float* __restrict__ x0) {
    __shared__ float sp[4][8];
    __shared__ float se[4];
    const int tid  = threadIdx.x;
    const int warp = tid >> 5;
    const int lane = tid & 31;

    if (blockIdx.x < 128) {
        // ------------- W0h: [8192 x 4096] halfs, row = 512 uint4 -----------
        const int rowBase = blockIdx.x * 64;
        const uint4* Wp = (const uint4*)g_W0h;
        float xfA[8], xfB[8];
        {
            const float4* xv = (const float4*)g_x1;
            float4 a = xv[2 * tid],         b = xv[2 * tid + 1];
            float4 c = xv[2 * tid + 512],   d = xv[2 * tid + 513];
            xfA[0]=a.x; xfA[1]=a.y; xfA[2]=a.z; xfA[3]=a.w;
            xfA[4]=b.x; xfA[5]=b.y; xfA[6]=b.z; xfA[7]=b.w;
            xfB[0]=c.x; xfB[1]=c.y; xfB[2]=c.z; xfB[3]=c.w;
            xfB[4]=d.x; xfB[5]=d.y; xfB[6]=d.z; xfB[7]=d.w;
        }
        float accA[8], accB[8];
        #pragma unroll
        for (int j = 0; j < 8; j++) { accA[j] = 0.f; accB[j] = 0.f; }

        uint4 b0[8], b1[8];
        #pragma unroll
        for (int r = 0; r < 4; r++) {
            b0[2*r]   = Wp[(size_t)(rowBase + r) * 512 + tid];
            b0[2*r+1] = Wp[(size_t)(rowBase + r) * 512 + tid + 256];
        }
        #pragma unroll 1
        for (int t = 0; t < 16; t += 2) {
            const int rb0 = rowBase + t * 4;
            W0_TILE(b0, b1, rb0, true, rb0 + 4);
            W0_TILE(b1, b0, rb0 + 4, t + 2 < 16, rb0 + 8);
        }
        #pragma unroll
        for (int j = 0; j < 8; j++) atomicAdd(&g_g1[8 * tid + j], accA[j]);
        #pragma unroll
        for (int j = 0; j < 8; j++) atomicAdd(&g_g1[8 * (tid + 256) + j], accB[j]);
    } else {
        // ------------- W1h: [4096 x 8192] halfs, row = 1024 uint4 ----------
        const int rowBase = (blockIdx.x - 128) * 32;
        const uint4* Wp = (const uint4*)g_W1h;
        float xf[32];
        {
            const float4* xv = (const float4*)g_x2;
            #pragma unroll
            for (int k = 0; k < 4; k++) {
                float4 a = xv[2 * (tid + 256 * k)];
                float4 b = xv[2 * (tid + 256 * k) + 1];
                xf[8*k+0]=a.x; xf[8*k+1]=a.y; xf[8*k+2]=a.z; xf[8*k+3]=a.w;
                xf[8*k+4]=b.x; xf[8*k+5]=b.y; xf[8*k+6]=b.z; xf[8*k+7]=b.w;
            }
        }
        float acc[32];
        #pragma unroll
        for (int j = 0; j < 32; j++) acc[j] = 0.f;

        uint4 b0[8], b1[8];
        #pragma unroll
        for (int r = 0; r < 2; r++)
            #pragma unroll
            for (int k = 0; k < 4; k++)
                b0[4*r+k] = Wp[(size_t)(rowBase + r) * 1024 + tid + 256 * k];
        #pragma unroll 1
        for (int t = 0; t < 16; t += 2) {
            const int rb0 = rowBase + t * 2;
            W1_TILE(b0, b1, rb0, true, rb0 + 2);
            W1_TILE(b1, b0, rb0 + 2, t + 2 < 16, rb0 + 4);
        }
        #pragma unroll
        for (int k = 0; k < 4; k++)
            #pragma unroll
            for (int j = 0; j < 8; j++)
                atomicAdd(&g_g2[8 * (tid + 256 * k) + j], acc[8 * k + j]);
    }
    step_epilogue(256);
}

// ---------------------------------------------------------------------------
// Final: err = ||x0 - tanh(W0@x1)||^2 + ||x1 - tanh(W1@x2)||^2 + ||x2||^2
// fp16 weights, warp-per-row.
// ---------------------------------------------------------------------------
__global__ void __launch_bounds__(256) k_final_h(const float* __restrict__ x0,
                                                 float* __restrict__ out) {
    __shared__ float s_part[8];
    const int warpInBlock = threadIdx.x >> 5;
    const int warp = (blockIdx.x * blockDim.x + threadIdx.x) >> 5;
    const int lane = threadIdx.x & 31;

    float local = 0.f;
    if (warp < N0) {
        const uint4* row = (const uint4*)g_W0h + (size_t)warp * 512;
        const float4* xv = (const float4*)g_x1;
        float acc = 0.f;
        #pragma unroll 4
        for (int i = lane; i < 512; i += 32) {
            uint4 w = row[i];
            float4 a = xv[2 * i], b = xv[2 * i + 1];
            float xf[8] = {a.x, a.y, a.z, a.w, b.x, b.y, b.z, b.w};
            acc += dot8(w, xf);
        }
        #pragma unroll
        for (int o = 16; o; o >>= 1) acc += __shfl_xor_sync(0xFFFFFFFFu, acc, o);
        if (lane == 0) {
            float e = x0[warp] - tanhf(acc);
            float x2v = g_x2[warp];
            local = e * e + x2v * x2v;
        }
    } else {
        const int r = warp - N0;
        const uint4* row = (const uint4*)g_W1h + (size_t)r * 1024;
        const float4* xv = (const float4*)g_x2;
        float acc = 0.f;
        #pragma unroll 4
        for (int i = lane; i < 1024; i += 32) {
            uint4 w = row[i];
            float4 a = xv[2 * i], b = xv[2 * i + 1];
            float xf[8] = {a.x, a.y, a.z, a.w, b.x, b.y, b.z, b.w};
            acc += dot8(w, xf);
        }
        #pragma unroll
        for (int o = 16; o; o >>= 1) acc += __shfl_xor_sync(0xFFFFFFFFu, acc, o);
        if (lane == 0) {
            float e = g_x1[r] - tanhf(acc);
            local = e * e;
        }
    }

    if (lane == 0) s_part[warpInBlock] = local;
    __syncthreads();
    if (threadIdx.x == 0) {
        float s = 0.f;
        #pragma unroll
        for (int w = 0; w < 8; w++) s += s_part[w];
        atomicAdd(out, s);
    }
}

// ---------------------------------------------------------------------------
extern "C" void kernel_launch(void* const* d_in, const int* in_sizes, int n_in,
                              void* d_out, int out_size) {
    const float* x0 = (const float*)d_in[0];
    const float* W0 = (const float*)d_in[1];
    const float* W1 = (const float*)d_in[2];
    float* out = (float*)d_out;

    k_init<<<32, 256>>>(out);
    k_step1<<<256, 512>>>(x0, W0, W1);          // fp32 step + fp16 conversion
    for (int s = 0; s < 8; s++)
        k_step_h<<<256, 256>>>(x0);             // fp16 steps, double-buffered
    k_final_h<<<(N0 + N1) / 8, 256>>>(x0, out); // fp16 final error
}